// round 17
// baseline (speedup 1.0000x reference)
#include <cuda_runtime.h>
#include <cuda_bf16.h>

// CovarianceResidualError — grid-stride dual-stream + L2::256B prefetch hint:
//   a_i = graph_emb[i,0];  ACC_j = sum_i e_ij*a_i;  SE_j = sum_i e_ij;  SA = sum_i a_i
//   out = -sum_j |ACC_j - SA*SE_j/N|
//
// DRAM busy 63% @ 5TB/s means DRAM keeps up when fed (7.9TB/s effective
// while active) -- the L2-miss->MC request path is the gap. ld.global.nc
// .L2::256B doubles the L2 fetch granule, halving MC command rate and
// improving row locality. Epilogue fused to a single float2 smem pass.
// Deterministic int64 (2^40) atomic combine; ticket-elected last CTA
// finalizes and re-zeros for the next graph replay.

#define NROWS 131072
#define OCOLS 256
#define DCOLS 128
#define NB 512
#define NSTEPS 32                          // 131072 rows / (512 CTA * 8 rows)

#define SCALE    1099511627776.0f          // 2^40
#define INVSCALE (1.0 / 1099511627776.0)

__device__ unsigned long long g_iacc[OCOLS];
__device__ unsigned long long g_ise [OCOLS];
__device__ unsigned long long g_isa;
__device__ unsigned int g_ct = 0;

__device__ __forceinline__ unsigned long long q40(float v) {
    return (unsigned long long)(long long)llrintf(v * SCALE);
}

// streaming read with 256B L2 fetch-granularity hint
__device__ __forceinline__ float4 ldg_nc256(const float4* p) {
    float4 v;
    asm("ld.global.nc.L2::256B.v4.f32 {%0, %1, %2, %3}, [%4];"
        : "=f"(v.x), "=f"(v.y), "=f"(v.z), "=f"(v.w)
        : "l"(p));
    return v;
}

__global__ void __launch_bounds__(256, 4)
cov_kernel(const float* __restrict__ ge, const float4* __restrict__ err4,
           float* __restrict__ out)
{
    __shared__ float2 red2[4 * OCOLS];     // 8 KB fused (acc,se) reduction
    __shared__ float  fin[OCOLS];          // final-stage scratch
    __shared__ float  ssa[4];
    __shared__ unsigned int s_ticket;

    const int tid = threadIdx.x;
    const int w   = tid >> 5;          // warp 0..7
    const int l   = tid & 31;          // lane
    const int tx  = tid & 63;          // column group (fixed all kernel)
    const int ty  = tid >> 6;          // row phase 0..3
    const int bid = blockIdx.x;

    // CTA's 8-row sub-window base within each 4096-row step window
    const int rbase = bid * 8;

    float4 acc1 = make_float4(0.f,0.f,0.f,0.f), acc2 = acc1;
    float4 se1  = acc1, se2 = acc1;
    float  sa   = 0.f;

    #pragma unroll 4
    for (int k = 0; k < NSTEPS; ++k) {
        const int row = k * 4096 + rbase + ty;        // stream 1: row ty
        float av = 0.f;
        if (l < 2)
            av = __ldcs(&ge[(size_t)(row + 4 * l) * DCOLS]);
        const float a1 = __shfl_sync(0xffffffffu, av, 0);
        const float a2 = __shfl_sync(0xffffffffu, av, 1);

        const float4 e1 = ldg_nc256(&err4[(size_t)row * (OCOLS / 4) + tx]);
        const float4 e2 = ldg_nc256(&err4[(size_t)(row + 4) * (OCOLS / 4) + tx]);

        acc1.x = fmaf(e1.x, a1, acc1.x); acc1.y = fmaf(e1.y, a1, acc1.y);
        acc1.z = fmaf(e1.z, a1, acc1.z); acc1.w = fmaf(e1.w, a1, acc1.w);
        se1.x += e1.x; se1.y += e1.y; se1.z += e1.z; se1.w += e1.w;

        acc2.x = fmaf(e2.x, a2, acc2.x); acc2.y = fmaf(e2.y, a2, acc2.y);
        acc2.z = fmaf(e2.z, a2, acc2.z); acc2.w = fmaf(e2.w, a2, acc2.w);
        se2.x += e2.x; se2.y += e2.y; se2.z += e2.z; se2.w += e2.w;

        if ((w & 1) == 0) sa += a1 + a2;   // rows counted once (even warps)
    }

    // merge dual streams
    const float4 acc = make_float4(acc1.x + acc2.x, acc1.y + acc2.y,
                                   acc1.z + acc2.z, acc1.w + acc2.w);
    const float4 se  = make_float4(se1.x + se2.x, se1.y + se2.y,
                                   se1.z + se2.z, se1.w + se2.w);

    if ((w & 1) == 0 && l == 0) ssa[w >> 1] = sa;

    // ---- fused (acc,se) phase reduction: single smem pass ----
    __syncthreads();
    red2[ty * OCOLS + 4 * tx + 0] = make_float2(acc.x, se.x);
    red2[ty * OCOLS + 4 * tx + 1] = make_float2(acc.y, se.y);
    red2[ty * OCOLS + 4 * tx + 2] = make_float2(acc.z, se.z);
    red2[ty * OCOLS + 4 * tx + 3] = make_float2(acc.w, se.w);
    __syncthreads();
    const float2 p0 = red2[tid];
    const float2 p1 = red2[OCOLS + tid];
    const float2 p2 = red2[2 * OCOLS + tid];
    const float2 p3 = red2[3 * OCOLS + tid];
    const float accTot = p0.x + p1.x + p2.x + p3.x;
    const float seTot  = p0.y + p1.y + p2.y + p3.y;

    // Deterministic global accumulation (order-independent integer adds)
    atomicAdd(&g_iacc[tid], q40(accTot));
    atomicAdd(&g_ise [tid], q40(seTot));
    if (tid == 0)
        atomicAdd(&g_isa, q40(ssa[0] + ssa[1] + ssa[2] + ssa[3]));

    __syncthreads();
    if (tid == 0) {
        __threadfence();
        s_ticket = atomicAdd(&g_ct, 1u);
    }
    __syncthreads();

    // ---- last-finishing CTA finalizes ----
    if (s_ticket == NB - 1) {
        __threadfence();
        const double A  = (double)(long long)g_iacc[tid] * INVSCALE;
        const double S  = (double)(long long)g_ise [tid] * INVSCALE;
        const double kk = ((double)(long long)g_isa * INVSCALE) / (double)NROWS;

        fin[tid] = (float)fabs(A - kk * S);
        __syncthreads();
        #pragma unroll
        for (int st = 128; st > 0; st >>= 1) {
            if (tid < st) fin[tid] += fin[tid + st];
            __syncthreads();
        }
        if (tid == 0) out[0] = -fin[0];

        // re-zero for the next graph replay
        g_iacc[tid] = 0ull;
        g_ise [tid] = 0ull;
        if (tid == 0) { g_isa = 0ull; g_ct = 0u; }
        __threadfence();
    }
}

extern "C" void kernel_launch(void* const* d_in, const int* in_sizes, int n_in,
                              void* d_out, int out_size)
{
    const float* ge  = nullptr;   // graph_emb (N x 128)
    const float* err = nullptr;   // errors    (N x 256)
    for (int i = 0; i < n_in; ++i) {
        if (in_sizes[i] == NROWS * DCOLS) ge  = (const float*)d_in[i];
        else if (in_sizes[i] == NROWS * OCOLS) err = (const float*)d_in[i];
    }

    cov_kernel<<<NB, 256>>>(ge, (const float4*)err, (float*)d_out);
}